// round 16
// baseline (speedup 1.0000x reference)
#include <cuda_runtime.h>
#include <cuda_fp16.h>
#include <cuda_fp8.h>
#include <mma.h>
#include <math.h>

using namespace nvcuda;

#define NMAX 100000
#define EMAX 1600000
#define HDIM 128
#define NGRAPH 64
#define BN_EPS 1e-5f
#define SCAN_NB 240

// dynamic smem layout for fused MLP kernel
#define M2_T_OFF    0          // T  [128][136] half = 34816
#define M2_W_OFF    34816      // Ws [128][136] half = 34816
#define M2_SBN_OFF  69632      // sbn [256] float = 1024
#define M2_PB_OFF   70656      // pbuf [8][128] float = 4096
#define M2_BG_OFF   74752      // bgr [128] int = 512
#define M2_PC_OFF   75264      // pcnt [8] float = 32
#define M2_SMEM     75392

// ---------------- static device scratch ----------------
__device__ __half        g_embh[4ll * NMAX * HDIM];
__device__ unsigned char g_embf8[4ll * NMAX * HDIM];
__device__ __half        g_zh[(size_t)NMAX * HDIM];
__device__ __half        g_wh[8 * 16384];
__device__ int    g_deg[NMAX];
__device__ int    g_cursor[NMAX];
__device__ int    g_rowptr[NMAX + 1];
__device__ int    g_csr[EMAX];
__device__ int    g_bsum[SCAN_NB];
__device__ float  g_bn[4 * 256];
__device__ float  g_pool[NGRAPH * 512];
__device__ float  g_cnt[NGRAPH];

// ---------------- zero + weight conversion ----------------
__global__ void k_init(int n, const float* __restrict__ c1W1, const float* __restrict__ c1W2,
                       const float* __restrict__ cW1, const float* __restrict__ cW2) {
    int i = blockIdx.x * blockDim.x + threadIdx.x;
    int stride = gridDim.x * blockDim.x;
    for (int j = i; j < n; j += stride) g_deg[j] = 0;
    for (int j = i; j < 4 * 256; j += stride) g_bn[j] = 0.0f;
    for (int j = i; j < NGRAPH * 512; j += stride) g_pool[j] = 0.0f;
    for (int j = i; j < NGRAPH; j += stride) g_cnt[j] = 0.0f;
    for (int idx = i; idx < 8 * 16384; idx += stride) {
        int slot = idx >> 14;
        int off = idx & 16383;
        float v = 0.0f;
        if (slot == 0) { if (off < 2048) v = c1W1[off]; }
        else if (slot == 1) v = c1W2[off];
        else {
            int w = (slot - 2) >> 1;
            v = (slot & 1) ? cW2[w * 16384 + off] : cW1[w * 16384 + off];
        }
        g_wh[idx] = __float2half(v);
    }
}

// ---------------- CSR build ----------------
__global__ void k_count(const int* __restrict__ dst, int e) {
    int i = blockIdx.x * blockDim.x + threadIdx.x;
    if (i < e) atomicAdd(&g_deg[dst[i]], 1);
}

__global__ void k_scan1(int n, int chunk, int tch) {
    __shared__ int s[256];
    int tid = threadIdx.x;
    int bstart = blockIdx.x * chunk;
    int bend = min(bstart + chunk, n);
    int start = bstart + tid * tch;
    int end = min(start + tch, bend);
    int sum = 0;
    for (int i = start; i < end; i++) sum += g_deg[i];
    s[tid] = sum;
    __syncthreads();
    for (int off = 128; off > 0; off >>= 1) {
        if (tid < off) s[tid] += s[tid + off];
        __syncthreads();
    }
    if (tid == 0) g_bsum[blockIdx.x] = s[0];
}

__global__ void k_scan2(int n) {
    __shared__ int s[SCAN_NB];
    int tid = threadIdx.x;
    int v = (tid < SCAN_NB) ? g_bsum[tid] : 0;
    if (tid < SCAN_NB) s[tid] = v;
    __syncthreads();
    for (int off = 1; off < SCAN_NB; off <<= 1) {
        int t = (tid < SCAN_NB && tid >= off) ? s[tid - off] : 0;
        __syncthreads();
        if (tid < SCAN_NB) s[tid] += t;
        __syncthreads();
    }
    if (tid < SCAN_NB) g_bsum[tid] = s[tid] - v;
    if (tid == SCAN_NB - 1) g_rowptr[n] = s[tid];
}

__global__ void k_scan3(int n, int chunk, int tch) {
    __shared__ int s[256];
    int tid = threadIdx.x;
    int bstart = blockIdx.x * chunk;
    int bend = min(bstart + chunk, n);
    int start = bstart + tid * tch;
    int end = min(start + tch, bend);
    int sum = 0;
    for (int i = start; i < end; i++) sum += g_deg[i];
    s[tid] = sum;
    __syncthreads();
    for (int off = 1; off < 256; off <<= 1) {
        int t = (tid >= off) ? s[tid - off] : 0;
        __syncthreads();
        s[tid] += t;
        __syncthreads();
    }
    int base = g_bsum[blockIdx.x] + s[tid] - sum;
    for (int i = start; i < end; i++) {
        g_rowptr[i] = base;
        g_cursor[i] = base;
        base += g_deg[i];
    }
}

__global__ void k_fill(const int* __restrict__ src, const int* __restrict__ dst, int e) {
    int i = blockIdx.x * blockDim.x + threadIdx.x;
    if (i < e) {
        int pos = atomicAdd(&g_cursor[dst[i]], 1);
        g_csr[pos] = src[i];
    }
}

// ---------------- aggregation, layer 1 (F=16, raw x) -> fp16 z; masked-tail gathers ----------------
__global__ void k_agg16(const float* __restrict__ x, const float* __restrict__ eps_p, int n) {
    int gid = blockIdx.x * blockDim.x + threadIdx.x;
    int node = gid >> 4;
    int lane16 = gid & 15;
    if (node >= n) return;
    int lane = threadIdx.x & 31;
    int gbase = lane & 16;
    unsigned int mask = 0xFFFFu << gbase;
    float eps1 = 1.0f + __ldg(eps_p);
    float acc = eps1 * __ldg(&x[(size_t)node * 16 + lane16]);
    int s = g_rowptr[node], e = g_rowptr[node + 1];
    for (int i = s; i < e; i += 8) {
        int k = i + lane16;
        int my = (lane16 < 8) ? g_csr[(k < e) ? k : s] : 0;
        float v[8];
#pragma unroll
        for (int j = 0; j < 8; j++) {
            int idx = __shfl_sync(mask, my, gbase + j);
            v[j] = __ldg(&x[(size_t)idx * 16 + lane16]);
        }
#pragma unroll
        for (int j = 0; j < 8; j++)
            if (i + j < e) acc += v[j];
    }
    g_zh[(size_t)node * 16 + lane16] = __float2half(acc);
}

// ---------------- aggregation H=128: fp8 gather (masked tail) + fp16 self + BN affine ----------------
__global__ void k_agg128(const __half* __restrict__ uh, const unsigned char* __restrict__ uf8,
                         const float* __restrict__ gamma, const float* __restrict__ beta,
                         const float* __restrict__ bn, const float* __restrict__ eps_p,
                         float inv_n, int n) {
    int warp = (blockIdx.x * blockDim.x + threadIdx.x) >> 5;
    int lane = threadIdx.x & 31;
    if (warp >= n) return;
    int f0 = lane * 4;
    float4 ga = *(const float4*)&gamma[f0];
    float4 be = *(const float4*)&beta[f0];
    float m0 = bn[f0 + 0] * inv_n, m1 = bn[f0 + 1] * inv_n;
    float m2 = bn[f0 + 2] * inv_n, m3 = bn[f0 + 3] * inv_n;
    float r0 = rsqrtf(bn[128 + f0 + 0] * inv_n - m0 * m0 + BN_EPS);
    float r1 = rsqrtf(bn[128 + f0 + 1] * inv_n - m1 * m1 + BN_EPS);
    float r2 = rsqrtf(bn[128 + f0 + 2] * inv_n - m2 * m2 + BN_EPS);
    float r3 = rsqrtf(bn[128 + f0 + 3] * inv_n - m3 * m3 + BN_EPS);
    float s0 = ga.x * r0, t0 = be.x - s0 * m0;
    float s1 = ga.y * r1, t1 = be.y - s1 * m1;
    float s2 = ga.z * r2, t2 = be.z - s2 * m2;
    float s3 = ga.w * r3, t3 = be.w - s3 * m3;

    float eps1 = 1.0f + __ldg(eps_p);
    const uint2* uh2 = (const uint2*)uh;
    uint2 sv = uh2[(size_t)warp * 32 + lane];
    float2 sp = __half22float2(*(__half2*)&sv.x), sq = __half22float2(*(__half2*)&sv.y);
    float ax = 0.f, ay = 0.f, az = 0.f, aw = 0.f;

    const unsigned int* u8 = (const unsigned int*)uf8;
    int sidx = g_rowptr[warp], eidx = g_rowptr[warp + 1];
    for (int i = sidx; i < eidx; i += 8) {
        int idx[8];
#pragma unroll
        for (int j = 0; j < 8; j++) {
            int k = i + j;
            idx[j] = g_csr[(k < eidx) ? k : sidx];
        }
        unsigned int vv[8];
#pragma unroll
        for (int j = 0; j < 8; j++) vv[j] = u8[(size_t)idx[j] * 32 + lane];
#pragma unroll
        for (int j = 0; j < 8; j++) {
            if (i + j < eidx) {
                __half2_raw h01 = __nv_cvt_fp8x2_to_halfraw2((__nv_fp8x2_storage_t)(vv[j] & 0xffff), __NV_E4M3);
                __half2_raw h23 = __nv_cvt_fp8x2_to_halfraw2((__nv_fp8x2_storage_t)(vv[j] >> 16), __NV_E4M3);
                float2 p = __half22float2(*(__half2*)&h01);
                float2 q = __half22float2(*(__half2*)&h23);
                ax += p.x; ay += p.y; az += q.x; aw += q.y;
            }
        }
    }
    float deg = (float)(eidx - sidx);
    float tc = eps1 + deg;
    float rx = s0 * (eps1 * sp.x + ax) + tc * t0;
    float ry = s1 * (eps1 * sp.y + ay) + tc * t1;
    float rz = s2 * (eps1 * sq.x + az) + tc * t2;
    float rw = s3 * (eps1 * sq.y + aw) + tc * t3;
    uint2 outv;
    *(__half2*)&outv.x = __floats2half2_rn(rx, ry);
    *(__half2*)&outv.y = __floats2half2_rn(rz, rw);
    ((uint2*)g_zh)[(size_t)warp * 32 + lane] = outv;
}

// ---------------- Fused MLP + segment-pooled epilogue ----------------
__global__ void __launch_bounds__(256)
k_mlp_tc(const __half* __restrict__ A, const __half* __restrict__ W1,
         const float* __restrict__ b1, const __half* __restrict__ W2,
         const float* __restrict__ b2, __half* __restrict__ Ch,
         unsigned char* __restrict__ Ch8,
         float* __restrict__ bnslot,
         const int* __restrict__ batchv, float* __restrict__ poolslab,
         float* __restrict__ cntp, int n, int K1) {
    extern __shared__ char smem[];
    __half (*T)[136]  = (__half(*)[136])(smem + M2_T_OFF);
    __half (*Ws)[136] = (__half(*)[136])(smem + M2_W_OFF);
    float  *sbn       = (float*)(smem + M2_SBN_OFF);
    float  (*pbuf)[128] = (float(*)[128])(smem + M2_PB_OFF);
    int    *bgr       = (int*)(smem + M2_BG_OFF);
    float  *pcnt      = (float*)(smem + M2_PC_OFF);

    int tid = threadIdx.x;
    int wid = tid >> 5;
    int warp_row = wid >> 2;
    int warp_col = wid & 3;
    int row0 = blockIdx.x * 128;
    int erow = tid >> 4;
    int ecg = tid & 15;

    // ---- load A into T, W1 into Ws; init pool smem ----
    {
        int kv = K1 >> 3;
        int total = 128 * kv;
        for (int idx = tid; idx < total; idx += 256) {
            int row = idx / kv;
            int col = (idx % kv) * 8;
            int gr = row0 + row;
            uint4 v = make_uint4(0, 0, 0, 0);
            if (gr < n) v = *(const uint4*)&A[(size_t)gr * K1 + col];
            *(uint4*)&T[row][col] = v;
        }
        for (int idx = tid; idx < K1 * 16; idx += 256) {
            int kr = idx >> 4, col = (idx & 15) * 8;
            *(uint4*)&Ws[kr][col] = *(const uint4*)&W1[(size_t)kr * 128 + col];
        }
        for (int idx = tid; idx < 8 * 128; idx += 256) ((float*)pbuf)[idx] = 0.0f;
        if (tid < 8) pcnt[tid] = 0.0f;
        if (tid < 128) {
            int gr = row0 + tid;
            bgr[tid] = (gr < n) ? batchv[gr] : -1;
        }
    }
    __syncthreads();

    // ---- stage 1: acc = A @ W1 ----
    wmma::fragment<wmma::accumulator, 16, 16, 16, __half> acc[4][2];
#pragma unroll
    for (int r = 0; r < 4; r++)
#pragma unroll
        for (int c = 0; c < 2; c++) wmma::fill_fragment(acc[r][c], __float2half(0.0f));

    for (int ks = 0; ks < K1; ks += 16) {
        wmma::fragment<wmma::matrix_a, 16, 16, 16, __half, wmma::row_major> af[4];
        wmma::fragment<wmma::matrix_b, 16, 16, 16, __half, wmma::row_major> bf[2];
#pragma unroll
        for (int r = 0; r < 4; r++)
            wmma::load_matrix_sync(af[r], &T[warp_row * 64 + r * 16][ks], 136);
#pragma unroll
        for (int c = 0; c < 2; c++)
            wmma::load_matrix_sync(bf[c], &Ws[ks][warp_col * 32 + c * 16], 136);
#pragma unroll
        for (int r = 0; r < 4; r++)
#pragma unroll
            for (int c = 0; c < 2; c++)
                wmma::mma_sync(acc[r][c], af[r], bf[c], acc[r][c]);
    }
    __syncthreads();

#pragma unroll
    for (int r = 0; r < 4; r++)
#pragma unroll
        for (int c = 0; c < 2; c++)
            wmma::store_matrix_sync(&T[warp_row * 64 + r * 16][warp_col * 32 + c * 16],
                                    acc[r][c], 136, wmma::mem_row_major);
    for (int idx = tid; idx < 2048; idx += 256) {
        int kr = idx >> 4, col = (idx & 15) * 8;
        *(uint4*)&Ws[kr][col] = *(const uint4*)&W2[(size_t)kr * 128 + col];
    }
    __syncthreads();

    // bias1 + relu elementwise on T
    {
        __half2 bh[4];
#pragma unroll
        for (int j = 0; j < 4; j++)
            bh[j] = __floats2half2_rn(b1[ecg * 8 + 2 * j], b1[ecg * 8 + 2 * j + 1]);
        __half2 zero2 = __floats2half2_rn(0.f, 0.f);
#pragma unroll
        for (int it = 0; it < 8; it++) {
            int row = erow + it * 16;
            uint4 h = *(uint4*)&T[row][ecg * 8];
            __half2* hp = (__half2*)&h;
#pragma unroll
            for (int j = 0; j < 4; j++) hp[j] = __hmax2(__hadd2(hp[j], bh[j]), zero2);
            *(uint4*)&T[row][ecg * 8] = h;
        }
    }
    __syncthreads();

    // ---- stage 2: acc = T @ W2 ----
#pragma unroll
    for (int r = 0; r < 4; r++)
#pragma unroll
        for (int c = 0; c < 2; c++) wmma::fill_fragment(acc[r][c], __float2half(0.0f));

#pragma unroll
    for (int ks = 0; ks < 128; ks += 16) {
        wmma::fragment<wmma::matrix_a, 16, 16, 16, __half, wmma::row_major> af[4];
        wmma::fragment<wmma::matrix_b, 16, 16, 16, __half, wmma::row_major> bf[2];
#pragma unroll
        for (int r = 0; r < 4; r++)
            wmma::load_matrix_sync(af[r], &T[warp_row * 64 + r * 16][ks], 136);
#pragma unroll
        for (int c = 0; c < 2; c++)
            wmma::load_matrix_sync(bf[c], &Ws[ks][warp_col * 32 + c * 16], 136);
#pragma unroll
        for (int r = 0; r < 4; r++)
#pragma unroll
            for (int c = 0; c < 2; c++)
                wmma::mma_sync(acc[r][c], af[r], bf[c], acc[r][c]);
    }
    __syncthreads();

#pragma unroll
    for (int r = 0; r < 4; r++)
#pragma unroll
        for (int c = 0; c < 2; c++)
            wmma::store_matrix_sync(&T[warp_row * 64 + r * 16][warp_col * 32 + c * 16],
                                    acc[r][c], 136, wmma::mem_row_major);
    __syncthreads();

    // final epilogue: bias2 + relu + writeout + BN stats + segment-pooled pooling
    {
        __half2 bh[4];
#pragma unroll
        for (int j = 0; j < 4; j++)
            bh[j] = __floats2half2_rn(b2[ecg * 8 + 2 * j], b2[ecg * 8 + 2 * j + 1]);
        __half2 zero2 = __floats2half2_rn(0.f, 0.f);
        float bsm[8], bq[8], pa[8];
#pragma unroll
        for (int j = 0; j < 8; j++) { bsm[j] = 0.f; bq[j] = 0.f; pa[j] = 0.f; }
        int g0 = bgr[0];
        int curg = -1;
        float pc = 0.f;

#pragma unroll
        for (int it = 0; it < 8; it++) {
            int row = erow + it * 16;
            int gr = row0 + row;
            if (gr < n) {
                uint4 h = *(uint4*)&T[row][ecg * 8];
                __half2* hp = (__half2*)&h;
                float2 fv[4];
#pragma unroll
                for (int j = 0; j < 4; j++) {
                    hp[j] = __hmax2(__hadd2(hp[j], bh[j]), zero2);
                    fv[j] = __half22float2(hp[j]);
                    bsm[2 * j] += fv[j].x;  bq[2 * j] += fv[j].x * fv[j].x;
                    bsm[2 * j + 1] += fv[j].y;  bq[2 * j + 1] += fv[j].y * fv[j].y;
                }
                *(uint4*)&Ch[(size_t)gr * 128 + ecg * 8] = h;
                if (Ch8) {
                    unsigned short p0 = __nv_cvt_float2_to_fp8x2(fv[0], __NV_SATFINITE, __NV_E4M3);
                    unsigned short p1 = __nv_cvt_float2_to_fp8x2(fv[1], __NV_SATFINITE, __NV_E4M3);
                    unsigned short p2 = __nv_cvt_float2_to_fp8x2(fv[2], __NV_SATFINITE, __NV_E4M3);
                    unsigned short p3 = __nv_cvt_float2_to_fp8x2(fv[3], __NV_SATFINITE, __NV_E4M3);
                    uint2 f8;
                    f8.x = (unsigned int)p0 | ((unsigned int)p1 << 16);
                    f8.y = (unsigned int)p2 | ((unsigned int)p3 << 16);
                    *(uint2*)&Ch8[(size_t)gr * 128 + ecg * 8] = f8;
                }
                int g = bgr[row];
                if (g != curg) {
                    if (curg >= 0) {
                        int gl = curg - g0;
                        if (gl >= 0 && gl < 8) {
#pragma unroll
                            for (int j = 0; j < 8; j++) atomicAdd(&pbuf[gl][ecg * 8 + j], pa[j]);
                            if (cntp && ecg == 0) atomicAdd(&pcnt[gl], pc);
                        } else {
#pragma unroll
                            for (int j = 0; j < 8; j++) atomicAdd(&poolslab[(size_t)curg * 512 + ecg * 8 + j], pa[j]);
                            if (cntp && ecg == 0) atomicAdd(&cntp[curg], pc);
                        }
#pragma unroll
                        for (int j = 0; j < 8; j++) pa[j] = 0.f;
                        pc = 0.f;
                    }
                    curg = g;
                }
#pragma unroll
                for (int j = 0; j < 4; j++) { pa[2 * j] += fv[j].x; pa[2 * j + 1] += fv[j].y; }
                pc += 1.f;
            }
        }
        if (curg >= 0) {
            int gl = curg - g0;
            if (gl >= 0 && gl < 8) {
#pragma unroll
                for (int j = 0; j < 8; j++) atomicAdd(&pbuf[gl][ecg * 8 + j], pa[j]);
                if (cntp && ecg == 0) atomicAdd(&pcnt[gl], pc);
            } else {
#pragma unroll
                for (int j = 0; j < 8; j++) atomicAdd(&poolslab[(size_t)curg * 512 + ecg * 8 + j], pa[j]);
                if (cntp && ecg == 0) atomicAdd(&cntp[curg], pc);
            }
        }

        sbn[tid] = 0.0f;
        __syncthreads();
#pragma unroll
        for (int j = 0; j < 8; j++) {
            atomicAdd(&sbn[ecg * 8 + j], bsm[j]);
            atomicAdd(&sbn[128 + ecg * 8 + j], bq[j]);
        }
        __syncthreads();
        atomicAdd(&bnslot[tid], sbn[tid]);

        for (int idx = tid; idx < 8 * 128; idx += 256) {
            int gl = idx >> 7, col = idx & 127;
            float v = pbuf[gl][col];
            if (v != 0.0f) {
                int g = g0 + gl;
                if (g < NGRAPH) atomicAdd(&poolslab[(size_t)g * 512 + col], v);
            }
        }
        if (cntp && tid < 8) {
            float c = pcnt[tid];
            int g = g0 + tid;
            if (c != 0.0f && g < NGRAPH) atomicAdd(&cntp[g], c);
        }
    }
}

// ---------------- classifier with BN affine on pooled means ----------------
__global__ void k_classifier(const float* __restrict__ W1, const float* __restrict__ b1,
                             const float* __restrict__ W2, const float* __restrict__ b2,
                             const float* __restrict__ W3, const float* __restrict__ b3,
                             const float* __restrict__ W4, const float* __restrict__ b4,
                             const float* __restrict__ c1g, const float* __restrict__ c1b,
                             const float* __restrict__ cg, const float* __restrict__ cb,
                             float inv_n, float* __restrict__ out) {
    __shared__ float emb[512], h1[256], h2[128], h3[128], logits[10];
    int g = blockIdx.x;
    int tid = threadIdx.x;
    float cnt = fmaxf(g_cnt[g], 1.0f);
    for (int f = tid; f < 512; f += 256) {
        int slab = f >> 7, col = f & 127;
        const float* G = (slab == 0) ? c1g : cg + (slab - 1) * 128;
        const float* B = (slab == 0) ? c1b : cb + (slab - 1) * 128;
        float m = g_bn[slab * 256 + col] * inv_n;
        float r = rsqrtf(g_bn[slab * 256 + 128 + col] * inv_n - m * m + BN_EPS);
        float s = G[col] * r;
        float t = B[col] - s * m;
        emb[f] = s * (g_pool[g * 512 + f] / cnt) + t;
    }
    __syncthreads();
    {
        float a = b1[tid];
        for (int k = 0; k < 512; k++) a += emb[k] * W1[k * 256 + tid];
        h1[tid] = fmaxf(a, 0.f);
    }
    __syncthreads();
    if (tid < 128) {
        float a = b2[tid];
        for (int k = 0; k < 256; k++) a += h1[k] * W2[k * 128 + tid];
        h2[tid] = fmaxf(a, 0.f);
    }
    __syncthreads();
    if (tid < 128) {
        float a = b3[tid];
        for (int k = 0; k < 128; k++) a += h2[k] * W3[k * 128 + tid];
        h3[tid] = fmaxf(a, 0.f);
    }
    __syncthreads();
    if (tid < 10) {
        float a = b4[tid];
        for (int k = 0; k < 128; k++) a += h3[k] * W4[k * 10 + tid];
        logits[tid] = a;
    }
    __syncthreads();
    if (tid == 0) {
        float mx = logits[0];
        for (int c = 1; c < 10; c++) mx = fmaxf(mx, logits[c]);
        float se = 0.f;
        for (int c = 0; c < 10; c++) se += expf(logits[c] - mx);
        float lse = logf(se) + mx;
        for (int c = 0; c < 10; c++) out[g * 10 + c] = logits[c] - lse;
    }
}

// ---------------- launch orchestration ----------------
extern "C" void kernel_launch(void* const* d_in, const int* in_sizes, int n_in,
                              void* d_out, int out_size) {
    const float* x     = (const float*)d_in[0];
    const int*   ei    = (const int*)d_in[1];
    const int*   batch = (const int*)d_in[2];
    const float* c1W1 = (const float*)d_in[3];
    const float* c1b1 = (const float*)d_in[4];
    const float* c1W2 = (const float*)d_in[5];
    const float* c1b2 = (const float*)d_in[6];
    const float* c1g  = (const float*)d_in[7];
    const float* c1b  = (const float*)d_in[8];
    const float* c1e  = (const float*)d_in[9];
    const float* cW1  = (const float*)d_in[10];
    const float* cb1  = (const float*)d_in[11];
    const float* cW2  = (const float*)d_in[12];
    const float* cb2  = (const float*)d_in[13];
    const float* cg   = (const float*)d_in[14];
    const float* cb   = (const float*)d_in[15];
    const float* ce   = (const float*)d_in[16];
    const float* lW1 = (const float*)d_in[17];
    const float* lb1 = (const float*)d_in[18];
    const float* lW2 = (const float*)d_in[19];
    const float* lb2 = (const float*)d_in[20];
    const float* lW3 = (const float*)d_in[21];
    const float* lb3 = (const float*)d_in[22];
    const float* lW4 = (const float*)d_in[23];
    const float* lb4 = (const float*)d_in[24];
    float* out = (float*)d_out;

    int n = in_sizes[0] / 16;
    int e = in_sizes[1] / 2;
    if (n > NMAX) n = NMAX;
    if (e > EMAX) e = EMAX;
    const int* src = ei;
    const int* dst = ei + e;
    float inv_n = 1.0f / (float)n;

    __half* zh_ptr;    cudaGetSymbolAddress((void**)&zh_ptr, g_zh);
    __half* embh_ptr;  cudaGetSymbolAddress((void**)&embh_ptr, g_embh);
    unsigned char* embf8_ptr; cudaGetSymbolAddress((void**)&embf8_ptr, g_embf8);
    __half* wh_ptr;    cudaGetSymbolAddress((void**)&wh_ptr, g_wh);
    float*  bn_ptr;    cudaGetSymbolAddress((void**)&bn_ptr, g_bn);
    float*  pool_ptr;  cudaGetSymbolAddress((void**)&pool_ptr, g_pool);
    float*  cnt_ptr;   cudaGetSymbolAddress((void**)&cnt_ptr, g_cnt);

    static int smem_set = 0;
    if (!smem_set) {
        cudaFuncSetAttribute(k_mlp_tc, cudaFuncAttributeMaxDynamicSharedMemorySize, M2_SMEM);
        smem_set = 1;
    }

    k_init<<<256, 256>>>(n, c1W1, c1W2, cW1, cW2);
    k_count<<<(e + 255) / 256, 256>>>(dst, e);

    int chunk = (n + SCAN_NB - 1) / SCAN_NB;
    int tch = (chunk + 255) / 256;
    k_scan1<<<SCAN_NB, 256>>>(n, chunk, tch);
    k_scan2<<<1, 256>>>(n);
    k_scan3<<<SCAN_NB, 256>>>(n, chunk, tch);

    k_fill<<<(e + 255) / 256, 256>>>(src, dst, e);

    int gemm_blocks = (n + 127) / 128;

    // Layer 1 (F=16 input); counts computed here
    k_agg16<<<(n * 16 + 255) / 256, 256>>>(x, c1e, n);
    k_mlp_tc<<<gemm_blocks, 256, M2_SMEM>>>(zh_ptr, wh_ptr + 0 * 16384, c1b1,
                                            wh_ptr + 1 * 16384, c1b2,
                                            embh_ptr, embf8_ptr, bn_ptr,
                                            batch, pool_ptr + 0 * 128, cnt_ptr, n, 16);

    // Layers 2-4
    for (int l = 1; l < 4; l++) {
        int i = l - 1;
        const float* gprev = (l == 1) ? c1g : cg + (l - 2) * 128;
        const float* bprev = (l == 1) ? c1b : cb + (l - 2) * 128;
        k_agg128<<<(n * 32 + 255) / 256, 256>>>(
            embh_ptr + (size_t)(l - 1) * NMAX * HDIM,
            embf8_ptr + (size_t)(l - 1) * NMAX * HDIM,
            gprev, bprev, bn_ptr + (l - 1) * 256, ce + i, inv_n, n);
        unsigned char* mirror = (l < 3) ? (embf8_ptr + (size_t)l * NMAX * HDIM) : (unsigned char*)nullptr;
        k_mlp_tc<<<gemm_blocks, 256, M2_SMEM>>>(zh_ptr, wh_ptr + (2 + 2 * i) * 16384, cb1 + i * 128,
                                                wh_ptr + (3 + 2 * i) * 16384, cb2 + i * 128,
                                                embh_ptr + (size_t)l * NMAX * HDIM,
                                                mirror, bn_ptr + l * 256,
                                                batch, pool_ptr + l * 128, (float*)nullptr, n, 128);
    }

    k_classifier<<<NGRAPH, 256>>>(lW1, lb1, lW2, lb2, lW3, lb3, lW4, lb4,
                                  c1g, c1b, cg, cb, inv_n, out);
}

// round 17
// speedup vs baseline: 1.1459x; 1.1459x over previous
#include <cuda_runtime.h>
#include <cuda_fp16.h>
#include <cuda_fp8.h>
#include <mma.h>
#include <math.h>

using namespace nvcuda;

#define NMAX 100000
#define EMAX 1600000
#define HDIM 128
#define NGRAPH 64
#define BN_EPS 1e-5f
#define SCAN_NB 240

// dynamic smem layout for fused MLP kernel
#define M2_T_OFF    0          // T  [128][136] half = 34816
#define M2_W_OFF    34816      // Ws [128][136] half = 34816
#define M2_SBN_OFF  69632      // sbn [256] float = 1024
#define M2_PB_OFF   70656      // pbuf [8][128] float = 4096
#define M2_BG_OFF   74752      // bgr [128] int = 512
#define M2_PC_OFF   75264      // pcnt [8] float = 32
#define M2_SMEM     75392

// ---------------- static device scratch ----------------
__device__ unsigned char g_embf8[4ll * NMAX * HDIM];   // fp8 e4m3 layer outputs (sole copy)
__device__ __half        g_zh[(size_t)NMAX * HDIM];    // aggregation output (MLP input)
__device__ __half        g_wh[8 * 16384];
__device__ int    g_deg[NMAX];
__device__ int    g_cursor[NMAX];
__device__ int    g_rowptr[NMAX + 1];
__device__ int    g_csr[EMAX];
__device__ int    g_bsum[SCAN_NB];
__device__ float  g_bn[4 * 256];
__device__ float  g_pool[NGRAPH * 512];
__device__ float  g_cnt[NGRAPH];

// ---------------- zero + weight conversion ----------------
__global__ void k_init(int n, const float* __restrict__ c1W1, const float* __restrict__ c1W2,
                       const float* __restrict__ cW1, const float* __restrict__ cW2) {
    int i = blockIdx.x * blockDim.x + threadIdx.x;
    int stride = gridDim.x * blockDim.x;
    for (int j = i; j < n; j += stride) g_deg[j] = 0;
    for (int j = i; j < 4 * 256; j += stride) g_bn[j] = 0.0f;
    for (int j = i; j < NGRAPH * 512; j += stride) g_pool[j] = 0.0f;
    for (int j = i; j < NGRAPH; j += stride) g_cnt[j] = 0.0f;
    for (int idx = i; idx < 8 * 16384; idx += stride) {
        int slot = idx >> 14;
        int off = idx & 16383;
        float v = 0.0f;
        if (slot == 0) { if (off < 2048) v = c1W1[off]; }
        else if (slot == 1) v = c1W2[off];
        else {
            int w = (slot - 2) >> 1;
            v = (slot & 1) ? cW2[w * 16384 + off] : cW1[w * 16384 + off];
        }
        g_wh[idx] = __float2half(v);
    }
}

// ---------------- CSR build ----------------
__global__ void k_count(const int* __restrict__ dst, int e) {
    int i = blockIdx.x * blockDim.x + threadIdx.x;
    if (i < e) atomicAdd(&g_deg[dst[i]], 1);
}

__global__ void k_scan1(int n, int chunk, int tch) {
    __shared__ int s[256];
    int tid = threadIdx.x;
    int bstart = blockIdx.x * chunk;
    int bend = min(bstart + chunk, n);
    int start = bstart + tid * tch;
    int end = min(start + tch, bend);
    int sum = 0;
    for (int i = start; i < end; i++) sum += g_deg[i];
    s[tid] = sum;
    __syncthreads();
    for (int off = 128; off > 0; off >>= 1) {
        if (tid < off) s[tid] += s[tid + off];
        __syncthreads();
    }
    if (tid == 0) g_bsum[blockIdx.x] = s[0];
}

__global__ void k_scan2(int n) {
    __shared__ int s[SCAN_NB];
    int tid = threadIdx.x;
    int v = (tid < SCAN_NB) ? g_bsum[tid] : 0;
    if (tid < SCAN_NB) s[tid] = v;
    __syncthreads();
    for (int off = 1; off < SCAN_NB; off <<= 1) {
        int t = (tid < SCAN_NB && tid >= off) ? s[tid - off] : 0;
        __syncthreads();
        if (tid < SCAN_NB) s[tid] += t;
        __syncthreads();
    }
    if (tid < SCAN_NB) g_bsum[tid] = s[tid] - v;
    if (tid == SCAN_NB - 1) g_rowptr[n] = s[tid];
}

__global__ void k_scan3(int n, int chunk, int tch) {
    __shared__ int s[256];
    int tid = threadIdx.x;
    int bstart = blockIdx.x * chunk;
    int bend = min(bstart + chunk, n);
    int start = bstart + tid * tch;
    int end = min(start + tch, bend);
    int sum = 0;
    for (int i = start; i < end; i++) sum += g_deg[i];
    s[tid] = sum;
    __syncthreads();
    for (int off = 1; off < 256; off <<= 1) {
        int t = (tid >= off) ? s[tid - off] : 0;
        __syncthreads();
        s[tid] += t;
        __syncthreads();
    }
    int base = g_bsum[blockIdx.x] + s[tid] - sum;
    for (int i = start; i < end; i++) {
        g_rowptr[i] = base;
        g_cursor[i] = base;
        base += g_deg[i];
    }
}

__global__ void k_fill(const int* __restrict__ src, const int* __restrict__ dst, int e) {
    int i = blockIdx.x * blockDim.x + threadIdx.x;
    if (i < e) {
        int pos = atomicAdd(&g_cursor[dst[i]], 1);
        g_csr[pos] = src[i];
    }
}

// ---------------- aggregation, layer 1 (F=16, raw x) -> fp16 z ----------------
__global__ void k_agg16(const float* __restrict__ x, const float* __restrict__ eps_p, int n) {
    int gid = blockIdx.x * blockDim.x + threadIdx.x;
    int node = gid >> 4;
    int lane16 = gid & 15;
    if (node >= n) return;
    int lane = threadIdx.x & 31;
    int gbase = lane & 16;
    unsigned int mask = 0xFFFFu << gbase;
    float eps1 = 1.0f + __ldg(eps_p);
    float acc = eps1 * __ldg(&x[(size_t)node * 16 + lane16]);
    int s = g_rowptr[node], e = g_rowptr[node + 1];
    int i = s;
    for (; i + 8 <= e; i += 8) {
        int my = (lane16 < 8) ? g_csr[i + lane16] : 0;
        float v[8];
#pragma unroll
        for (int j = 0; j < 8; j++) {
            int idx = __shfl_sync(mask, my, gbase + j);
            v[j] = __ldg(&x[(size_t)idx * 16 + lane16]);
        }
#pragma unroll
        for (int j = 0; j < 8; j++) acc += v[j];
    }
    for (; i < e; i++) acc += __ldg(&x[(size_t)g_csr[i] * 16 + lane16]);
    g_zh[(size_t)node * 16 + lane16] = __float2half(acc);
}

// ---------------- aggregation H=128: fp8 gather + fp8 self + BN affine ----------------
__global__ void k_agg128(const unsigned char* __restrict__ uf8,
                         const float* __restrict__ gamma, const float* __restrict__ beta,
                         const float* __restrict__ bn, const float* __restrict__ eps_p,
                         float inv_n, int n) {
    int warp = (blockIdx.x * blockDim.x + threadIdx.x) >> 5;
    int lane = threadIdx.x & 31;
    if (warp >= n) return;
    int f0 = lane * 4;
    float4 ga = *(const float4*)&gamma[f0];
    float4 be = *(const float4*)&beta[f0];
    float m0 = bn[f0 + 0] * inv_n, m1 = bn[f0 + 1] * inv_n;
    float m2 = bn[f0 + 2] * inv_n, m3 = bn[f0 + 3] * inv_n;
    float r0 = rsqrtf(bn[128 + f0 + 0] * inv_n - m0 * m0 + BN_EPS);
    float r1 = rsqrtf(bn[128 + f0 + 1] * inv_n - m1 * m1 + BN_EPS);
    float r2 = rsqrtf(bn[128 + f0 + 2] * inv_n - m2 * m2 + BN_EPS);
    float r3 = rsqrtf(bn[128 + f0 + 3] * inv_n - m3 * m3 + BN_EPS);
    float s0 = ga.x * r0, t0 = be.x - s0 * m0;
    float s1 = ga.y * r1, t1 = be.y - s1 * m1;
    float s2 = ga.z * r2, t2 = be.z - s2 * m2;
    float s3 = ga.w * r3, t3 = be.w - s3 * m3;

    float eps1 = 1.0f + __ldg(eps_p);
    const unsigned int* u8 = (const unsigned int*)uf8;
    // self term from fp8
    unsigned int svu = u8[(size_t)warp * 32 + lane];
    __half2_raw s01 = __nv_cvt_fp8x2_to_halfraw2((__nv_fp8x2_storage_t)(svu & 0xffff), __NV_E4M3);
    __half2_raw s23 = __nv_cvt_fp8x2_to_halfraw2((__nv_fp8x2_storage_t)(svu >> 16), __NV_E4M3);
    float2 sp = __half22float2(*(__half2*)&s01), sq = __half22float2(*(__half2*)&s23);
    float ax = 0.f, ay = 0.f, az = 0.f, aw = 0.f;

    int sidx = g_rowptr[warp], eidx = g_rowptr[warp + 1];
    int i = sidx;
    for (; i + 8 <= eidx; i += 8) {
        int idx[8];
#pragma unroll
        for (int j = 0; j < 8; j++) idx[j] = g_csr[i + j];
        unsigned int vv[8];
#pragma unroll
        for (int j = 0; j < 8; j++) vv[j] = u8[(size_t)idx[j] * 32 + lane];
#pragma unroll
        for (int j = 0; j < 8; j++) {
            __half2_raw h01 = __nv_cvt_fp8x2_to_halfraw2((__nv_fp8x2_storage_t)(vv[j] & 0xffff), __NV_E4M3);
            __half2_raw h23 = __nv_cvt_fp8x2_to_halfraw2((__nv_fp8x2_storage_t)(vv[j] >> 16), __NV_E4M3);
            float2 p = __half22float2(*(__half2*)&h01);
            float2 q = __half22float2(*(__half2*)&h23);
            ax += p.x; ay += p.y; az += q.x; aw += q.y;
        }
    }
    for (; i < eidx; i++) {
        unsigned int v = u8[(size_t)g_csr[i] * 32 + lane];
        __half2_raw h01 = __nv_cvt_fp8x2_to_halfraw2((__nv_fp8x2_storage_t)(v & 0xffff), __NV_E4M3);
        __half2_raw h23 = __nv_cvt_fp8x2_to_halfraw2((__nv_fp8x2_storage_t)(v >> 16), __NV_E4M3);
        float2 p = __half22float2(*(__half2*)&h01);
        float2 q = __half22float2(*(__half2*)&h23);
        ax += p.x; ay += p.y; az += q.x; aw += q.y;
    }
    float deg = (float)(eidx - sidx);
    float tc = eps1 + deg;
    float rx = s0 * (eps1 * sp.x + ax) + tc * t0;
    float ry = s1 * (eps1 * sp.y + ay) + tc * t1;
    float rz = s2 * (eps1 * sq.x + az) + tc * t2;
    float rw = s3 * (eps1 * sq.y + aw) + tc * t3;
    uint2 outv;
    *(__half2*)&outv.x = __floats2half2_rn(rx, ry);
    *(__half2*)&outv.y = __floats2half2_rn(rz, rw);
    ((uint2*)g_zh)[(size_t)warp * 32 + lane] = outv;
}

// ---------------- Fused MLP + segment-pooled epilogue (fp8-only output) ----------------
__global__ void __launch_bounds__(256)
k_mlp_tc(const __half* __restrict__ A, const __half* __restrict__ W1,
         const float* __restrict__ b1, const __half* __restrict__ W2,
         const float* __restrict__ b2,
         unsigned char* __restrict__ Ch8,
         float* __restrict__ bnslot,
         const int* __restrict__ batchv, float* __restrict__ poolslab,
         float* __restrict__ cntp, int n, int K1) {
    extern __shared__ char smem[];
    __half (*T)[136]  = (__half(*)[136])(smem + M2_T_OFF);
    __half (*Ws)[136] = (__half(*)[136])(smem + M2_W_OFF);
    float  *sbn       = (float*)(smem + M2_SBN_OFF);
    float  (*pbuf)[128] = (float(*)[128])(smem + M2_PB_OFF);
    int    *bgr       = (int*)(smem + M2_BG_OFF);
    float  *pcnt      = (float*)(smem + M2_PC_OFF);

    int tid = threadIdx.x;
    int wid = tid >> 5;
    int warp_row = wid >> 2;
    int warp_col = wid & 3;
    int row0 = blockIdx.x * 128;
    int erow = tid >> 4;
    int ecg = tid & 15;

    // ---- load A into T, W1 into Ws; init pool smem ----
    {
        int kv = K1 >> 3;
        int total = 128 * kv;
        for (int idx = tid; idx < total; idx += 256) {
            int row = idx / kv;
            int col = (idx % kv) * 8;
            int gr = row0 + row;
            uint4 v = make_uint4(0, 0, 0, 0);
            if (gr < n) v = *(const uint4*)&A[(size_t)gr * K1 + col];
            *(uint4*)&T[row][col] = v;
        }
        for (int idx = tid; idx < K1 * 16; idx += 256) {
            int kr = idx >> 4, col = (idx & 15) * 8;
            *(uint4*)&Ws[kr][col] = *(const uint4*)&W1[(size_t)kr * 128 + col];
        }
        for (int idx = tid; idx < 8 * 128; idx += 256) ((float*)pbuf)[idx] = 0.0f;
        if (tid < 8) pcnt[tid] = 0.0f;
        if (tid < 128) {
            int gr = row0 + tid;
            bgr[tid] = (gr < n) ? batchv[gr] : -1;
        }
    }
    __syncthreads();

    // ---- stage 1: acc = A @ W1 ----
    wmma::fragment<wmma::accumulator, 16, 16, 16, __half> acc[4][2];
#pragma unroll
    for (int r = 0; r < 4; r++)
#pragma unroll
        for (int c = 0; c < 2; c++) wmma::fill_fragment(acc[r][c], __float2half(0.0f));

    for (int ks = 0; ks < K1; ks += 16) {
        wmma::fragment<wmma::matrix_a, 16, 16, 16, __half, wmma::row_major> af[4];
        wmma::fragment<wmma::matrix_b, 16, 16, 16, __half, wmma::row_major> bf[2];
#pragma unroll
        for (int r = 0; r < 4; r++)
            wmma::load_matrix_sync(af[r], &T[warp_row * 64 + r * 16][ks], 136);
#pragma unroll
        for (int c = 0; c < 2; c++)
            wmma::load_matrix_sync(bf[c], &Ws[ks][warp_col * 32 + c * 16], 136);
#pragma unroll
        for (int r = 0; r < 4; r++)
#pragma unroll
            for (int c = 0; c < 2; c++)
                wmma::mma_sync(acc[r][c], af[r], bf[c], acc[r][c]);
    }
    __syncthreads();

#pragma unroll
    for (int r = 0; r < 4; r++)
#pragma unroll
        for (int c = 0; c < 2; c++)
            wmma::store_matrix_sync(&T[warp_row * 64 + r * 16][warp_col * 32 + c * 16],
                                    acc[r][c], 136, wmma::mem_row_major);
    for (int idx = tid; idx < 2048; idx += 256) {
        int kr = idx >> 4, col = (idx & 15) * 8;
        *(uint4*)&Ws[kr][col] = *(const uint4*)&W2[(size_t)kr * 128 + col];
    }
    __syncthreads();

    // bias1 + relu elementwise on T
    {
        __half2 bh[4];
#pragma unroll
        for (int j = 0; j < 4; j++)
            bh[j] = __floats2half2_rn(b1[ecg * 8 + 2 * j], b1[ecg * 8 + 2 * j + 1]);
        __half2 zero2 = __floats2half2_rn(0.f, 0.f);
#pragma unroll
        for (int it = 0; it < 8; it++) {
            int row = erow + it * 16;
            uint4 h = *(uint4*)&T[row][ecg * 8];
            __half2* hp = (__half2*)&h;
#pragma unroll
            for (int j = 0; j < 4; j++) hp[j] = __hmax2(__hadd2(hp[j], bh[j]), zero2);
            *(uint4*)&T[row][ecg * 8] = h;
        }
    }
    __syncthreads();

    // ---- stage 2: acc = T @ W2 ----
#pragma unroll
    for (int r = 0; r < 4; r++)
#pragma unroll
        for (int c = 0; c < 2; c++) wmma::fill_fragment(acc[r][c], __float2half(0.0f));

#pragma unroll
    for (int ks = 0; ks < 128; ks += 16) {
        wmma::fragment<wmma::matrix_a, 16, 16, 16, __half, wmma::row_major> af[4];
        wmma::fragment<wmma::matrix_b, 16, 16, 16, __half, wmma::row_major> bf[2];
#pragma unroll
        for (int r = 0; r < 4; r++)
            wmma::load_matrix_sync(af[r], &T[warp_row * 64 + r * 16][ks], 136);
#pragma unroll
        for (int c = 0; c < 2; c++)
            wmma::load_matrix_sync(bf[c], &Ws[ks][warp_col * 32 + c * 16], 136);
#pragma unroll
        for (int r = 0; r < 4; r++)
#pragma unroll
            for (int c = 0; c < 2; c++)
                wmma::mma_sync(acc[r][c], af[r], bf[c], acc[r][c]);
    }
    __syncthreads();

#pragma unroll
    for (int r = 0; r < 4; r++)
#pragma unroll
        for (int c = 0; c < 2; c++)
            wmma::store_matrix_sync(&T[warp_row * 64 + r * 16][warp_col * 32 + c * 16],
                                    acc[r][c], 136, wmma::mem_row_major);
    __syncthreads();

    // final epilogue: bias2 + relu + fp8 writeout + BN stats + segment-pooled pooling
    {
        __half2 bh[4];
#pragma unroll
        for (int j = 0; j < 4; j++)
            bh[j] = __floats2half2_rn(b2[ecg * 8 + 2 * j], b2[ecg * 8 + 2 * j + 1]);
        __half2 zero2 = __floats2half2_rn(0.f, 0.f);
        float bsm[8], bq[8], pa[8];
#pragma unroll
        for (int j = 0; j < 8; j++) { bsm[j] = 0.f; bq[j] = 0.f; pa[j] = 0.f; }
        int g0 = bgr[0];
        int curg = -1;
        float pc = 0.f;

#pragma unroll
        for (int it = 0; it < 8; it++) {
            int row = erow + it * 16;
            int gr = row0 + row;
            if (gr < n) {
                uint4 h = *(uint4*)&T[row][ecg * 8];
                __half2* hp = (__half2*)&h;
                float2 fv[4];
#pragma unroll
                for (int j = 0; j < 4; j++) {
                    hp[j] = __hmax2(__hadd2(hp[j], bh[j]), zero2);
                    fv[j] = __half22float2(hp[j]);
                    bsm[2 * j] += fv[j].x;  bq[2 * j] += fv[j].x * fv[j].x;
                    bsm[2 * j + 1] += fv[j].y;  bq[2 * j + 1] += fv[j].y * fv[j].y;
                }
                if (Ch8) {
                    unsigned short p0 = __nv_cvt_float2_to_fp8x2(fv[0], __NV_SATFINITE, __NV_E4M3);
                    unsigned short p1 = __nv_cvt_float2_to_fp8x2(fv[1], __NV_SATFINITE, __NV_E4M3);
                    unsigned short p2 = __nv_cvt_float2_to_fp8x2(fv[2], __NV_SATFINITE, __NV_E4M3);
                    unsigned short p3 = __nv_cvt_float2_to_fp8x2(fv[3], __NV_SATFINITE, __NV_E4M3);
                    uint2 f8;
                    f8.x = (unsigned int)p0 | ((unsigned int)p1 << 16);
                    f8.y = (unsigned int)p2 | ((unsigned int)p3 << 16);
                    *(uint2*)&Ch8[(size_t)gr * 128 + ecg * 8] = f8;
                }
                int g = bgr[row];
                if (g != curg) {
                    if (curg >= 0) {
                        int gl = curg - g0;
                        if (gl >= 0 && gl < 8) {
#pragma unroll
                            for (int j = 0; j < 8; j++) atomicAdd(&pbuf[gl][ecg * 8 + j], pa[j]);
                            if (cntp && ecg == 0) atomicAdd(&pcnt[gl], pc);
                        } else {
#pragma unroll
                            for (int j = 0; j < 8; j++) atomicAdd(&poolslab[(size_t)curg * 512 + ecg * 8 + j], pa[j]);
                            if (cntp && ecg == 0) atomicAdd(&cntp[curg], pc);
                        }
#pragma unroll
                        for (int j = 0; j < 8; j++) pa[j] = 0.f;
                        pc = 0.f;
                    }
                    curg = g;
                }
#pragma unroll
                for (int j = 0; j < 4; j++) { pa[2 * j] += fv[j].x; pa[2 * j + 1] += fv[j].y; }
                pc += 1.f;
            }
        }
        if (curg >= 0) {
            int gl = curg - g0;
            if (gl >= 0 && gl < 8) {
#pragma unroll
                for (int j = 0; j < 8; j++) atomicAdd(&pbuf[gl][ecg * 8 + j], pa[j]);
                if (cntp && ecg == 0) atomicAdd(&pcnt[gl], pc);
            } else {
#pragma unroll
                for (int j = 0; j < 8; j++) atomicAdd(&poolslab[(size_t)curg * 512 + ecg * 8 + j], pa[j]);
                if (cntp && ecg == 0) atomicAdd(&cntp[curg], pc);
            }
        }

        sbn[tid] = 0.0f;
        __syncthreads();
#pragma unroll
        for (int j = 0; j < 8; j++) {
            atomicAdd(&sbn[ecg * 8 + j], bsm[j]);
            atomicAdd(&sbn[128 + ecg * 8 + j], bq[j]);
        }
        __syncthreads();
        atomicAdd(&bnslot[tid], sbn[tid]);

        for (int idx = tid; idx < 8 * 128; idx += 256) {
            int gl = idx >> 7, col = idx & 127;
            float v = pbuf[gl][col];
            if (v != 0.0f) {
                int g = g0 + gl;
                if (g < NGRAPH) atomicAdd(&poolslab[(size_t)g * 512 + col], v);
            }
        }
        if (cntp && tid < 8) {
            float c = pcnt[tid];
            int g = g0 + tid;
            if (c != 0.0f && g < NGRAPH) atomicAdd(&cntp[g], c);
        }
    }
}

// ---------------- classifier with BN affine on pooled means ----------------
__global__ void k_classifier(const float* __restrict__ W1, const float* __restrict__ b1,
                             const float* __restrict__ W2, const float* __restrict__ b2,
                             const float* __restrict__ W3, const float* __restrict__ b3,
                             const float* __restrict__ W4, const float* __restrict__ b4,
                             const float* __restrict__ c1g, const float* __restrict__ c1b,
                             const float* __restrict__ cg, const float* __restrict__ cb,
                             float inv_n, float* __restrict__ out) {
    __shared__ float emb[512], h1[256], h2[128], h3[128], logits[10];
    int g = blockIdx.x;
    int tid = threadIdx.x;
    float cnt = fmaxf(g_cnt[g], 1.0f);
    for (int f = tid; f < 512; f += 256) {
        int slab = f >> 7, col = f & 127;
        const float* G = (slab == 0) ? c1g : cg + (slab - 1) * 128;
        const float* B = (slab == 0) ? c1b : cb + (slab - 1) * 128;
        float m = g_bn[slab * 256 + col] * inv_n;
        float r = rsqrtf(g_bn[slab * 256 + 128 + col] * inv_n - m * m + BN_EPS);
        float s = G[col] * r;
        float t = B[col] - s * m;
        emb[f] = s * (g_pool[g * 512 + f] / cnt) + t;
    }
    __syncthreads();
    {
        float a = b1[tid];
        for (int k = 0; k < 512; k++) a += emb[k] * W1[k * 256 + tid];
        h1[tid] = fmaxf(a, 0.f);
    }
    __syncthreads();
    if (tid < 128) {
        float a = b2[tid];
        for (int k = 0; k < 256; k++) a += h1[k] * W2[k * 128 + tid];
        h2[tid] = fmaxf(a, 0.f);
    }
    __syncthreads();
    if (tid < 128) {
        float a = b3[tid];
        for (int k = 0; k < 128; k++) a += h2[k] * W3[k * 128 + tid];
        h3[tid] = fmaxf(a, 0.f);
    }
    __syncthreads();
    if (tid < 10) {
        float a = b4[tid];
        for (int k = 0; k < 128; k++) a += h3[k] * W4[k * 10 + tid];
        logits[tid] = a;
    }
    __syncthreads();
    if (tid == 0) {
        float mx = logits[0];
        for (int c = 1; c < 10; c++) mx = fmaxf(mx, logits[c]);
        float se = 0.f;
        for (int c = 0; c < 10; c++) se += expf(logits[c] - mx);
        float lse = logf(se) + mx;
        for (int c = 0; c < 10; c++) out[g * 10 + c] = logits[c] - lse;
    }
}

// ---------------- launch orchestration ----------------
extern "C" void kernel_launch(void* const* d_in, const int* in_sizes, int n_in,
                              void* d_out, int out_size) {
    const float* x     = (const float*)d_in[0];
    const int*   ei    = (const int*)d_in[1];
    const int*   batch = (const int*)d_in[2];
    const float* c1W1 = (const float*)d_in[3];
    const float* c1b1 = (const float*)d_in[4];
    const float* c1W2 = (const float*)d_in[5];
    const float* c1b2 = (const float*)d_in[6];
    const float* c1g  = (const float*)d_in[7];
    const float* c1b  = (const float*)d_in[8];
    const float* c1e  = (const float*)d_in[9];
    const float* cW1  = (const float*)d_in[10];
    const float* cb1  = (const float*)d_in[11];
    const float* cW2  = (const float*)d_in[12];
    const float* cb2  = (const float*)d_in[13];
    const float* cg   = (const float*)d_in[14];
    const float* cb   = (const float*)d_in[15];
    const float* ce   = (const float*)d_in[16];
    const float* lW1 = (const float*)d_in[17];
    const float* lb1 = (const float*)d_in[18];
    const float* lW2 = (const float*)d_in[19];
    const float* lb2 = (const float*)d_in[20];
    const float* lW3 = (const float*)d_in[21];
    const float* lb3 = (const float*)d_in[22];
    const float* lW4 = (const float*)d_in[23];
    const float* lb4 = (const float*)d_in[24];
    float* out = (float*)d_out;

    int n = in_sizes[0] / 16;
    int e = in_sizes[1] / 2;
    if (n > NMAX) n = NMAX;
    if (e > EMAX) e = EMAX;
    const int* src = ei;
    const int* dst = ei + e;
    float inv_n = 1.0f / (float)n;

    __half* zh_ptr;    cudaGetSymbolAddress((void**)&zh_ptr, g_zh);
    unsigned char* embf8_ptr; cudaGetSymbolAddress((void**)&embf8_ptr, g_embf8);
    __half* wh_ptr;    cudaGetSymbolAddress((void**)&wh_ptr, g_wh);
    float*  bn_ptr;    cudaGetSymbolAddress((void**)&bn_ptr, g_bn);
    float*  pool_ptr;  cudaGetSymbolAddress((void**)&pool_ptr, g_pool);
    float*  cnt_ptr;   cudaGetSymbolAddress((void**)&cnt_ptr, g_cnt);

    static int smem_set = 0;
    if (!smem_set) {
        cudaFuncSetAttribute(k_mlp_tc, cudaFuncAttributeMaxDynamicSharedMemorySize, M2_SMEM);
        smem_set = 1;
    }

    k_init<<<256, 256>>>(n, c1W1, c1W2, cW1, cW2);
    k_count<<<(e + 255) / 256, 256>>>(dst, e);

    int chunk = (n + SCAN_NB - 1) / SCAN_NB;
    int tch = (chunk + 255) / 256;
    k_scan1<<<SCAN_NB, 256>>>(n, chunk, tch);
    k_scan2<<<1, 256>>>(n);
    k_scan3<<<SCAN_NB, 256>>>(n, chunk, tch);

    k_fill<<<(e + 255) / 256, 256>>>(src, dst, e);

    int gemm_blocks = (n + 127) / 128;

    // Layer 1 (F=16 input); counts computed here
    k_agg16<<<(n * 16 + 255) / 256, 256>>>(x, c1e, n);
    k_mlp_tc<<<gemm_blocks, 256, M2_SMEM>>>(zh_ptr, wh_ptr + 0 * 16384, c1b1,
                                            wh_ptr + 1 * 16384, c1b2,
                                            embf8_ptr + 0, bn_ptr,
                                            batch, pool_ptr + 0 * 128, cnt_ptr, n, 16);

    // Layers 2-4
    for (int l = 1; l < 4; l++) {
        int i = l - 1;
        const float* gprev = (l == 1) ? c1g : cg + (l - 2) * 128;
        const float* bprev = (l == 1) ? c1b : cb + (l - 2) * 128;
        k_agg128<<<(n * 32 + 255) / 256, 256>>>(
            embf8_ptr + (size_t)(l - 1) * NMAX * HDIM,
            gprev, bprev, bn_ptr + (l - 1) * 256, ce + i, inv_n, n);
        unsigned char* mirror = (l < 3) ? (embf8_ptr + (size_t)l * NMAX * HDIM) : (unsigned char*)nullptr;
        k_mlp_tc<<<gemm_blocks, 256, M2_SMEM>>>(zh_ptr, wh_ptr + (2 + 2 * i) * 16384, cb1 + i * 128,
                                                wh_ptr + (3 + 2 * i) * 16384, cb2 + i * 128,
                                                mirror, bn_ptr + l * 256,
                                                batch, pool_ptr + l * 128, (float*)nullptr, n, 128);
    }

    k_classifier<<<NGRAPH, 256>>>(lW1, lb1, lW2, lb2, lW3, lb3, lW4, lb4,
                                  c1g, c1b, cg, cb, inv_n, out);
}